// round 7
// baseline (speedup 1.0000x reference)
#include <cuda_runtime.h>

// Fully-fused RK4 step of 2D Burgers-type PDE, (8,2,1024,1024) fp32,
// periodic wrap, 4th-order cross stencils (radius 2).
//
// ONE kernel: per 64x32 output tile, compute s1 (44 rows x 22 f4cols),
// s2 (40x20), s3 (36x18) through ping-pong SMEM buffers, then k4 on the
// inner tile. RK accumulator lives in registers (owner-computes: each
// thread owns 2 inner rows of one float4 column in every stage; halo
// points are distributed as extra per-stage tasks).
// DRAM traffic: read h (~64MB + halo), write out (64MB). No global scratch.

#define IMW 1024
#define HW  (1024 * 1024)
#define NB  8

#define TX 64
#define TY 32

// SMEM buffer A: s1, rows -6..37 (44), fx -12..75 (88)
// SMEM buffer B: s2, rows -4..35 (40), fx  -8..71 (80)
// s3 reuses A storage: rows -2..33 (36), fx -4..67 (72)
#define A_ROWS 44
#define A_PITCH 88
#define B_ROWS 40
#define B_PITCH 80
#define C_PITCH 72
#define SMEM_FLOATS (2 * A_ROWS * A_PITCH + 2 * B_ROWS * B_PITCH)   // 14144
#define SMEM_BYTES  (SMEM_FLOATS * 4)                               // 56576

__device__ __forceinline__ float4 ld4(const float* __restrict__ p) {
    return *reinterpret_cast<const float4*>(p);
}
__device__ __forceinline__ void st4(float* __restrict__ p, float a, float b, float c, float d) {
    *reinterpret_cast<float4*>(p) = make_float4(a, b, c, d);
}
__device__ __forceinline__ void put4(float* d, float4 v) {
    d[0] = v.x; d[1] = v.y; d[2] = v.z; d[3] = v.w;
}

struct Par { float nu, UA, UB, VA, VB; };

// Global loader with periodic wrap (fx multiple of 4 -> aligned).
struct GL {
    const float* p; int x0, y0;
    __device__ __forceinline__ float4 ld(int r, int fx) const {
        return ld4(p + (((y0 + r) & 1023) << 10) + ((x0 + fx) & 1023));
    }
};
// SMEM loader (tile coords; halo baked into ro/co offsets).
struct SL {
    const float* s; int pitch, ro, co;
    __device__ __forceinline__ float4 ld(int r, int fx) const {
        return ld4(s + (r + ro) * pitch + fx + co);
    }
};

// 4-wide RHS. Window rows n2,n1,p1,p2 (center x), w[12] = {left4, center4, right4}.
__device__ __forceinline__ void rhs4(
    const float un2[4], const float un1[4], const float wu[12],
    const float up1[4], const float up2[4],
    const float vn2[4], const float vn1[4], const float wv[12],
    const float vp1[4], const float vp2[4],
    const Par p, float fu[4], float fv[4])
{
    const float inv_dx2 = 10000.0f;
    const float inv_dx  = 100.0f;
    const float c0 = -5.0f, c1 = 4.0f / 3.0f, c2 = -1.0f / 12.0f;
    const float d1 = 8.0f / 12.0f, d2 = 1.0f / 12.0f;
#pragma unroll
    for (int j = 0; j < 4; j++) {
        const float uc = wu[4 + j];
        const float vc = wv[4 + j];
        const float lap_u = (c0 * uc
                           + c1 * (un1[j] + up1[j] + wu[3 + j] + wu[5 + j])
                           + c2 * (un2[j] + up2[j] + wu[2 + j] + wu[6 + j])) * inv_dx2;
        const float lap_v = (c0 * vc
                           + c1 * (vn1[j] + vp1[j] + wv[3 + j] + wv[5 + j])
                           + c2 * (vn2[j] + vp2[j] + wv[2 + j] + wv[6 + j])) * inv_dx2;
        // "u_x" differentiates along H (rows) per reference convention:
        const float u_x = (d2 * (un2[j] - up2[j]) + d1 * (up1[j] - un1[j])) * inv_dx;
        const float v_x = (d2 * (vn2[j] - vp2[j]) + d1 * (vp1[j] - vn1[j])) * inv_dx;
        // "u_y" along W (columns):
        const float u_y = (d2 * (wu[2 + j] - wu[6 + j]) + d1 * (wu[5 + j] - wu[3 + j])) * inv_dx;
        const float v_y = (d2 * (wv[2 + j] - wv[6 + j]) + d1 * (wv[5 + j] - wv[3 + j])) * inv_dx;
        fu[j] = p.nu * lap_u + p.UA * uc * u_x + p.UB * vc * u_y;
        fv[j] = p.nu * lap_v + p.VA * uc * v_x + p.VB * vc * v_y;
    }
}

// Full 9-point cross gather + RHS at one float4 point (both channels).
// Also returns the field centers (cu, cv).
template <class L>
__device__ __forceinline__ void kpoint(
    const L& lu, const L& lv, int r, int fx, const Par& p,
    float fu[4], float fv[4], float cu[4], float cv[4])
{
    float un2[4], un1[4], up1[4], up2[4], wu[12];
    float vn2[4], vn1[4], vp1[4], vp2[4], wv[12];
    put4(un2, lu.ld(r - 2, fx));
    put4(un1, lu.ld(r - 1, fx));
    put4(wu + 4, lu.ld(r, fx));
    put4(up1, lu.ld(r + 1, fx));
    put4(up2, lu.ld(r + 2, fx));
    put4(wu + 0, lu.ld(r, fx - 4));
    put4(wu + 8, lu.ld(r, fx + 4));
    put4(vn2, lv.ld(r - 2, fx));
    put4(vn1, lv.ld(r - 1, fx));
    put4(wv + 4, lv.ld(r, fx));
    put4(vp1, lv.ld(r + 1, fx));
    put4(vp2, lv.ld(r + 2, fx));
    put4(wv + 0, lv.ld(r, fx - 4));
    put4(wv + 8, lv.ld(r, fx + 4));
    rhs4(un2, un1, wu, up1, up2, vn2, vn1, wv, vp1, vp2, p, fu, fv);
#pragma unroll
    for (int j = 0; j < 4; j++) { cu[j] = wu[4 + j]; cv[j] = wv[4 + j]; }
}

// Map halo task id -> (f4col c, row r) for region cols [C0,C1) x rows [R0,R1)
// minus inner [0,16) x [0,32). Returns false when id exceeds halo count.
template <int C0, int C1, int R0, int R1>
__device__ __forceinline__ bool halo_map(int id, int& c, int& r)
{
    constexpr int H  = R1 - R0;
    constexpr int nL = (-C0) * H;
    constexpr int nR = (C1 - 16) * H;
    constexpr int nT = (-R0) * 16;
    constexpr int nB = (R1 - 32) * 16;
    if (id < nL) { c = C0 + id / H; r = R0 + id % H; return true; }
    id -= nL;
    if (id < nR) { c = 16 + id / H; r = R0 + id % H; return true; }
    id -= nR;
    if (id < nT) { r = R0 + id / 16; c = id % 16; return true; }
    id -= nT;
    if (id < nB) { r = 32 + id / 16; c = id % 16; return true; }
    return false;
}

__global__ __launch_bounds__(256, 3) void rk4_fused_kernel(
    const float* __restrict__ h,
    float* __restrict__ out,
    const float* __restrict__ pRe,
    const float* __restrict__ pUA,
    const float* __restrict__ pUB,
    const float* __restrict__ pVA,
    const float* __restrict__ pVB)
{
    extern __shared__ float smem[];
    float* uA = smem;
    float* vA = uA + A_ROWS * A_PITCH;
    float* uB = vA + A_ROWS * A_PITCH;
    float* vB = uB + B_ROWS * B_PITCH;

    const int tid = threadIdx.x;
    const int g   = tid & 15;        // f4 column 0..15
    const int rc  = tid >> 4;        // row chunk 0..15 (rows 2rc, 2rc+1)
    const int x0  = blockIdx.x * TX;
    const int y0  = blockIdx.y * TY;
    const int base = blockIdx.z * 2 * HW;

    const Par p = { 0.001f / pRe[0], pUA[0], pUB[0], pVA[0], pVB[0] };

    const float* hu = h + base;
    const float* hv = hu + HW;
    const GL glu{hu, x0, y0};
    const GL glv{hv, x0, y0};

    float accu[2][4], accv[2][4];

    // ================= stage 1: k1 from h; s1 = h + 0.25 k1 -> A =================
    {
#pragma unroll
        for (int i = 0; i < 2; i++) {
            const int r = 2 * rc + i, fx = 4 * g;
            float fu[4], fv[4], cu[4], cv[4];
            kpoint(glu, glv, r, fx, p, fu, fv, cu, cv);
            const int ix = (r + 6) * A_PITCH + fx + 12;
            st4(uA + ix, cu[0] + 0.25f * fu[0], cu[1] + 0.25f * fu[1],
                         cu[2] + 0.25f * fu[2], cu[3] + 0.25f * fu[3]);
            st4(vA + ix, cv[0] + 0.25f * fv[0], cv[1] + 0.25f * fv[1],
                         cv[2] + 0.25f * fv[2], cv[3] + 0.25f * fv[3]);
#pragma unroll
            for (int j = 0; j < 4; j++) { accu[i][j] = fu[j]; accv[i][j] = fv[j]; }
        }
        for (int id = tid; id < 456; id += 256) {
            int c, r;
            halo_map<-3, 19, -6, 38>(id, c, r);
            const int fx = 4 * c;
            float fu[4], fv[4], cu[4], cv[4];
            kpoint(glu, glv, r, fx, p, fu, fv, cu, cv);
            const int ix = (r + 6) * A_PITCH + fx + 12;
            st4(uA + ix, cu[0] + 0.25f * fu[0], cu[1] + 0.25f * fu[1],
                         cu[2] + 0.25f * fu[2], cu[3] + 0.25f * fu[3]);
            st4(vA + ix, cv[0] + 0.25f * fv[0], cv[1] + 0.25f * fv[1],
                         cv[2] + 0.25f * fv[2], cv[3] + 0.25f * fv[3]);
        }
    }
    __syncthreads();

    // ================= stage 2: k2 from A; s2 = h + 0.25 k2 -> B =================
    {
        const SL alu{uA, A_PITCH, 6, 12};
        const SL alv{vA, A_PITCH, 6, 12};
#pragma unroll
        for (int i = 0; i < 2; i++) {
            const int r = 2 * rc + i, fx = 4 * g;
            float fu[4], fv[4], cu[4], cv[4];
            kpoint(alu, alv, r, fx, p, fu, fv, cu, cv);
            float hu4[4], hv4[4];
            put4(hu4, glu.ld(r, fx));
            put4(hv4, glv.ld(r, fx));
            const int ix = (r + 4) * B_PITCH + fx + 8;
            st4(uB + ix, hu4[0] + 0.25f * fu[0], hu4[1] + 0.25f * fu[1],
                         hu4[2] + 0.25f * fu[2], hu4[3] + 0.25f * fu[3]);
            st4(vB + ix, hv4[0] + 0.25f * fv[0], hv4[1] + 0.25f * fv[1],
                         hv4[2] + 0.25f * fv[2], hv4[3] + 0.25f * fv[3]);
#pragma unroll
            for (int j = 0; j < 4; j++) {
                accu[i][j] += 2.0f * fu[j];
                accv[i][j] += 2.0f * fv[j];
            }
        }
        for (int id = tid; id < 288; id += 256) {
            int c, r;
            halo_map<-2, 18, -4, 36>(id, c, r);
            const int fx = 4 * c;
            float fu[4], fv[4], cu[4], cv[4];
            kpoint(alu, alv, r, fx, p, fu, fv, cu, cv);
            float hu4[4], hv4[4];
            put4(hu4, glu.ld(r, fx));
            put4(hv4, glv.ld(r, fx));
            const int ix = (r + 4) * B_PITCH + fx + 8;
            st4(uB + ix, hu4[0] + 0.25f * fu[0], hu4[1] + 0.25f * fu[1],
                         hu4[2] + 0.25f * fu[2], hu4[3] + 0.25f * fu[3]);
            st4(vB + ix, hv4[0] + 0.25f * fv[0], hv4[1] + 0.25f * fv[1],
                         hv4[2] + 0.25f * fv[2], hv4[3] + 0.25f * fv[3]);
        }
    }
    __syncthreads();

    // ============ stage 3: k3 from B; s3 = h + 0.5 k3 -> A storage (C) ============
    {
        const SL blu{uB, B_PITCH, 4, 8};
        const SL blv{vB, B_PITCH, 4, 8};
#pragma unroll
        for (int i = 0; i < 2; i++) {
            const int r = 2 * rc + i, fx = 4 * g;
            float fu[4], fv[4], cu[4], cv[4];
            kpoint(blu, blv, r, fx, p, fu, fv, cu, cv);
            float hu4[4], hv4[4];
            put4(hu4, glu.ld(r, fx));
            put4(hv4, glv.ld(r, fx));
            const int ix = (r + 2) * C_PITCH + fx + 4;
            st4(uA + ix, hu4[0] + 0.5f * fu[0], hu4[1] + 0.5f * fu[1],
                         hu4[2] + 0.5f * fu[2], hu4[3] + 0.5f * fu[3]);
            st4(vA + ix, hv4[0] + 0.5f * fv[0], hv4[1] + 0.5f * fv[1],
                         hv4[2] + 0.5f * fv[2], hv4[3] + 0.5f * fv[3]);
#pragma unroll
            for (int j = 0; j < 4; j++) {
                accu[i][j] += 2.0f * fu[j];
                accv[i][j] += 2.0f * fv[j];
            }
        }
        for (int id = tid; id < 136; id += 256) {
            int c, r;
            halo_map<-1, 17, -2, 34>(id, c, r);
            const int fx = 4 * c;
            float fu[4], fv[4], cu[4], cv[4];
            kpoint(blu, blv, r, fx, p, fu, fv, cu, cv);
            float hu4[4], hv4[4];
            put4(hu4, glu.ld(r, fx));
            put4(hv4, glv.ld(r, fx));
            const int ix = (r + 2) * C_PITCH + fx + 4;
            st4(uA + ix, hu4[0] + 0.5f * fu[0], hu4[1] + 0.5f * fu[1],
                         hu4[2] + 0.5f * fu[2], hu4[3] + 0.5f * fu[3]);
            st4(vA + ix, hv4[0] + 0.5f * fv[0], hv4[1] + 0.5f * fv[1],
                         hv4[2] + 0.5f * fv[2], hv4[3] + 0.5f * fv[3]);
        }
    }
    __syncthreads();

    // ====== stage 4: k4 from C; out = h + (DT/6)*(k1 + 2k2 + 2k3 + k4) ======
    {
        const SL clu{uA, C_PITCH, 2, 4};
        const SL clv{vA, C_PITCH, 2, 4};
        const float w6 = 0.5f / 6.0f;
#pragma unroll
        for (int i = 0; i < 2; i++) {
            const int r = 2 * rc + i, fx = 4 * g;
            float fu[4], fv[4], cu[4], cv[4];
            kpoint(clu, clv, r, fx, p, fu, fv, cu, cv);
            float hu4[4], hv4[4];
            put4(hu4, glu.ld(r, fx));
            put4(hv4, glv.ld(r, fx));
            const int off = base + ((y0 + r) << 10) + x0 + fx;
            st4(out + off,
                hu4[0] + w6 * (accu[i][0] + fu[0]),
                hu4[1] + w6 * (accu[i][1] + fu[1]),
                hu4[2] + w6 * (accu[i][2] + fu[2]),
                hu4[3] + w6 * (accu[i][3] + fu[3]));
            st4(out + off + HW,
                hv4[0] + w6 * (accv[i][0] + fv[0]),
                hv4[1] + w6 * (accv[i][1] + fv[1]),
                hv4[2] + w6 * (accv[i][2] + fv[2]),
                hv4[3] + w6 * (accv[i][3] + fv[3]));
        }
    }
}

extern "C" void kernel_launch(void* const* d_in, const int* in_sizes, int n_in,
                              void* d_out, int out_size)
{
    const float* h = nullptr;
    const float* sc[5] = {nullptr, nullptr, nullptr, nullptr, nullptr};
    int nsc = 0;
    for (int i = 0; i < n_in; i++) {
        if (in_sizes[i] == NB * 2 * HW) {
            h = (const float*)d_in[i];
        } else if (nsc < 5) {
            sc[nsc++] = (const float*)d_in[i];
        }
    }
    const float* Re = sc[0];
    const float* UA = sc[1];
    const float* UB = sc[2];
    const float* VA = sc[3];
    const float* VB = sc[4];

    static bool attr_done = false;
    if (!attr_done) {
        cudaFuncSetAttribute(rk4_fused_kernel,
                             cudaFuncAttributeMaxDynamicSharedMemorySize, SMEM_BYTES);
        attr_done = true;
    }

    dim3 grid(IMW / TX, 1024 / TY, NB);   // 16 x 32 x 8 = 4096 blocks
    rk4_fused_kernel<<<grid, 256, SMEM_BYTES>>>(h, (float*)d_out, Re, UA, UB, VA, VB);
    (void)out_size;
}

// round 8
// speedup vs baseline: 1.5288x; 1.5288x over previous
#include <cuda_runtime.h>

// Fully-fused RK4 step of 2D Burgers-type PDE, (8,2,1024,1024) fp32,
// periodic wrap, 4th-order cross stencils (radius 2).
//
// One kernel, 64x32 output tile. Stage fields s1,s2,s3 live in SMEM
// (A -> B -> A ping-pong). Every stage is a set of column sweeps with a
// rolling 5-row register window (4 loads/point/channel instead of 7).
// The RK partial sum P = k1 + 2*k2 round-trips through d_out (written in
// stage 2, read in stage 4 by the same block -> L1/L2 resident).
// DRAM: read h (~77MB incl halo), write out (64MB); P round-trip stays in cache.

#define HW  (1024 * 1024)
#define NB  8

#define TX 64
#define TY 32

// SMEM buffers (floats):
//  A (s1): rows -6..37 (44) x cols -12..75 pad -> pitch 92, col ofs 12, row ofs 6
//  B (s2): rows -4..35 (40) x cols  -8..71 pad -> pitch 84, col ofs  8, row ofs 4
//  C (s3) reuses A:  rows -2..33 (36)          -> pitch 76, col ofs  4, row ofs 2
#define PA 92
#define PB 84
#define PC 76
#define A_FL (44 * PA)          // 4048 per channel
#define B_FL (40 * PB)          // 3360 per channel
#define SMEM_FLOATS (2 * A_FL + 2 * B_FL)   // 14816
#define SMEM_BYTES  (SMEM_FLOATS * 4)       // 59264

__device__ __forceinline__ float4 ld4(const float* __restrict__ p) {
    return *reinterpret_cast<const float4*>(p);
}
__device__ __forceinline__ void st4(float* __restrict__ p, float a, float b, float c, float d) {
    *reinterpret_cast<float4*>(p) = make_float4(a, b, c, d);
}
__device__ __forceinline__ void put4(float* d, float4 v) {
    d[0] = v.x; d[1] = v.y; d[2] = v.z; d[3] = v.w;
}

// Folded coefficients: a* = nu * lap_tap / dx^2 ; dd* = deriv_tap / dx.
struct Par { float a0, a1, a2, dd1, dd2, UA, UB, VA, VB; };

// Global loader, periodic wrap (fx multiple of 4 -> aligned float4).
struct GL {
    const float* p; int x0, y0;
    __device__ __forceinline__ float4 ld(int r, int fx) const {
        return ld4(p + (((y0 + r) & 1023) << 10) + ((x0 + fx) & 1023));
    }
};
// SMEM loader (tile coords, halo offsets baked in).
struct SL {
    const float* s; int pitch, rofs, cofs;
    __device__ __forceinline__ float4 ld(int r, int fx) const {
        return ld4(s + (r + rofs) * pitch + fx + cofs);
    }
};

__device__ __forceinline__ void rhs4(
    const float un2[4], const float un1[4], const float wu[12],
    const float up1[4], const float up2[4],
    const float vn2[4], const float vn1[4], const float wv[12],
    const float vp1[4], const float vp2[4],
    const Par& p, float fu[4], float fv[4])
{
#pragma unroll
    for (int j = 0; j < 4; j++) {
        const float uc = wu[4 + j];
        const float vc = wv[4 + j];
        const float lap_u = p.a0 * uc
                          + p.a1 * (un1[j] + up1[j] + wu[3 + j] + wu[5 + j])
                          + p.a2 * (un2[j] + up2[j] + wu[2 + j] + wu[6 + j]);
        const float lap_v = p.a0 * vc
                          + p.a1 * (vn1[j] + vp1[j] + wv[3 + j] + wv[5 + j])
                          + p.a2 * (vn2[j] + vp2[j] + wv[2 + j] + wv[6 + j]);
        // "u_x" differentiates along H (rows) per reference convention:
        const float u_x = p.dd2 * (un2[j] - up2[j]) + p.dd1 * (up1[j] - un1[j]);
        const float v_x = p.dd2 * (vn2[j] - vp2[j]) + p.dd1 * (vp1[j] - vn1[j]);
        // "u_y" along W (columns):
        const float u_y = p.dd2 * (wu[2 + j] - wu[6 + j]) + p.dd1 * (wu[5 + j] - wu[3 + j]);
        const float v_y = p.dd2 * (wv[2 + j] - wv[6 + j]) + p.dd1 * (wv[5 + j] - wv[3 + j]);
        fu[j] = lap_u + p.UA * uc * u_x + p.UB * vc * u_y;
        fv[j] = lap_v + p.VA * uc * v_x + p.VB * vc * v_y;
    }
}

#define ROT(n2, n1, c, p1, p2) \
    _Pragma("unroll") for (int j = 0; j < 4; j++) { \
        n2[j] = n1[j]; n1[j] = c[j]; c[j] = p1[j]; p1[j] = p2[j]; }

// Rolling column sweep: CH rows starting at r0, one float4 column fx.
// emit(r, fu, fv, cu, cv) is called per row with the RHS and field centers.
template <int CH, class LU, class LV, class F>
__device__ __forceinline__ void sweep_col(
    const LU& lu, const LV& lv, int fx, int r0, const Par& p, F&& emit)
{
    float un2[4], un1[4], uc[4], up1[4];
    float vn2[4], vn1[4], vc[4], vp1[4];
    put4(un2, lu.ld(r0 - 2, fx));
    put4(un1, lu.ld(r0 - 1, fx));
    put4(uc,  lu.ld(r0,     fx));
    put4(up1, lu.ld(r0 + 1, fx));
    put4(vn2, lv.ld(r0 - 2, fx));
    put4(vn1, lv.ld(r0 - 1, fx));
    put4(vc,  lv.ld(r0,     fx));
    put4(vp1, lv.ld(r0 + 1, fx));
#pragma unroll
    for (int i = 0; i < CH; i++) {
        const int r = r0 + i;
        float up2[4], vp2[4], wu[12], wv[12];
        put4(up2, lu.ld(r + 2, fx));
        put4(vp2, lv.ld(r + 2, fx));
        put4(wu + 0, lu.ld(r, fx - 4));
        put4(wu + 8, lu.ld(r, fx + 4));
        put4(wv + 0, lv.ld(r, fx - 4));
        put4(wv + 8, lv.ld(r, fx + 4));
#pragma unroll
        for (int j = 0; j < 4; j++) { wu[4 + j] = uc[j]; wv[4 + j] = vc[j]; }
        float fu[4], fv[4];
        rhs4(un2, un1, wu, up1, up2, vn2, vn1, wv, vp1, vp2, p, fu, fv);
        emit(r, fu, fv, uc, vc);
        ROT(un2, un1, uc, up1, up2);
        ROT(vn2, vn1, vc, vp1, vp2);
    }
}

__global__ __launch_bounds__(256, 3) void rk4_fused_kernel(
    const float* __restrict__ h,
    float* __restrict__ out,
    const float* __restrict__ pRe,
    const float* __restrict__ pUA,
    const float* __restrict__ pUB,
    const float* __restrict__ pVA,
    const float* __restrict__ pVB)
{
    extern __shared__ float smem[];
    float* uA = smem;
    float* vA = uA + A_FL;
    float* uB = vA + A_FL;
    float* vB = uB + B_FL;

    const int tid  = threadIdx.x;
    const int x0   = blockIdx.x * TX;
    const int y0   = blockIdx.y * TY;
    const int base = blockIdx.z * 2 * HW;

    const float nu = 0.001f / pRe[0];
    const Par p = { nu * -50000.0f,
                    nu * (40000.0f / 3.0f),
                    nu * (-10000.0f / 12.0f),
                    800.0f / 12.0f,
                    100.0f / 12.0f,
                    pUA[0], pUB[0], pVA[0], pVB[0] };

    const GL glu{h + base,      x0, y0};
    const GL glv{h + base + HW, x0, y0};

    // ===== stage 1: k1 from h; s1 = h + 0.25*k1 -> A  (22 cols x 44 rows) =====
    if (tid < 242) {                       // 22 cols x 11 chunks of 4
        const int cc = tid % 22;
        const int ch = tid / 22;
        const int fx = 4 * (cc - 3);
        const int r0 = -6 + 4 * ch;
        sweep_col<4>(glu, glv, fx, r0, p,
            [&](int r, const float fu[4], const float fv[4],
                const float cu[4], const float cv[4]) {
                const int ix = (r + 6) * PA + fx + 12;
                st4(uA + ix, cu[0] + 0.25f * fu[0], cu[1] + 0.25f * fu[1],
                             cu[2] + 0.25f * fu[2], cu[3] + 0.25f * fu[3]);
                st4(vA + ix, cv[0] + 0.25f * fv[0], cv[1] + 0.25f * fv[1],
                             cv[2] + 0.25f * fv[2], cv[3] + 0.25f * fv[3]);
            });
    }
    __syncthreads();

    // ===== stage 2: k2 from s1(A); s2 = h + 0.25*k2 -> B; P = k1+2k2 -> out ====
    if (tid < 200) {                       // 20 cols x 10 chunks of 4
        const int cc = tid % 20;
        const int ch = tid / 20;
        const int c  = cc - 2;
        const int fx = 4 * c;
        const int r0 = -4 + 4 * ch;
        const SL alu{uA, PA, 6, 12};
        const SL alv{vA, PA, 6, 12};
        sweep_col<4>(alu, alv, fx, r0, p,
            [&](int r, const float fu[4], const float fv[4],
                const float cu[4], const float cv[4]) {
                float hu4[4], hv4[4];
                put4(hu4, glu.ld(r, fx));
                put4(hv4, glv.ld(r, fx));
                const int ix = (r + 4) * PB + fx + 8;
                st4(uB + ix, hu4[0] + 0.25f * fu[0], hu4[1] + 0.25f * fu[1],
                             hu4[2] + 0.25f * fu[2], hu4[3] + 0.25f * fu[3]);
                st4(vB + ix, hv4[0] + 0.25f * fv[0], hv4[1] + 0.25f * fv[1],
                             hv4[2] + 0.25f * fv[2], hv4[3] + 0.25f * fv[3]);
                if ((unsigned)c < 16u && (unsigned)r < 32u) {
                    // k1 = 4*(s1_center - h); P = k1 + 2*k2
                    const int off = base + ((y0 + r) << 10) + x0 + fx;
                    st4(out + off,
                        4.0f * (cu[0] - hu4[0]) + 2.0f * fu[0],
                        4.0f * (cu[1] - hu4[1]) + 2.0f * fu[1],
                        4.0f * (cu[2] - hu4[2]) + 2.0f * fu[2],
                        4.0f * (cu[3] - hu4[3]) + 2.0f * fu[3]);
                    st4(out + off + HW,
                        4.0f * (cv[0] - hv4[0]) + 2.0f * fv[0],
                        4.0f * (cv[1] - hv4[1]) + 2.0f * fv[1],
                        4.0f * (cv[2] - hv4[2]) + 2.0f * fv[2],
                        4.0f * (cv[3] - hv4[3]) + 2.0f * fv[3]);
                }
            });
    }
    __syncthreads();

    // ===== stage 3: k3 from s2(B); s3 = h + 0.5*k3 -> A storage (C layout) =====
    if (tid < 162) {                       // 18 cols x 9 chunks of 4
        const int cc = tid % 18;
        const int ch = tid / 18;
        const int fx = 4 * (cc - 1);
        const int r0 = -2 + 4 * ch;
        const SL blu{uB, PB, 4, 8};
        const SL blv{vB, PB, 4, 8};
        sweep_col<4>(blu, blv, fx, r0, p,
            [&](int r, const float fu[4], const float fv[4],
                const float cu[4], const float cv[4]) {
                float hu4[4], hv4[4];
                put4(hu4, glu.ld(r, fx));
                put4(hv4, glv.ld(r, fx));
                const int ix = (r + 2) * PC + fx + 4;
                st4(uA + ix, hu4[0] + 0.5f * fu[0], hu4[1] + 0.5f * fu[1],
                             hu4[2] + 0.5f * fu[2], hu4[3] + 0.5f * fu[3]);
                st4(vA + ix, hv4[0] + 0.5f * fv[0], hv4[1] + 0.5f * fv[1],
                             hv4[2] + 0.5f * fv[2], hv4[3] + 0.5f * fv[3]);
            });
    }
    __syncthreads();

    // ===== stage 4: k4 from s3(C); out = h + (DT/6)*(P + 2*k3 + k4) =====
    {
        const int cc = tid & 15;           // 16 cols x 16 chunks of 2
        const int ch = tid >> 4;
        const int fx = 4 * cc;
        const int r0 = 2 * ch;
        const SL clu{uA, PC, 2, 4};
        const SL clv{vA, PC, 2, 4};
        const float w6 = 0.5f / 6.0f;
        sweep_col<2>(clu, clv, fx, r0, p,
            [&](int r, const float fu[4], const float fv[4],
                const float cu[4], const float cv[4]) {
                float hu4[4], hv4[4];
                put4(hu4, glu.ld(r, fx));
                put4(hv4, glv.ld(r, fx));
                const int off = base + ((y0 + r) << 10) + x0 + fx;
                float Pu[4], Pv[4];
                put4(Pu, ld4(out + off));
                put4(Pv, ld4(out + off + HW));
                // k3 = 2*(s3_center - h)
                st4(out + off,
                    hu4[0] + w6 * (Pu[0] + 4.0f * (cu[0] - hu4[0]) + fu[0]),
                    hu4[1] + w6 * (Pu[1] + 4.0f * (cu[1] - hu4[1]) + fu[1]),
                    hu4[2] + w6 * (Pu[2] + 4.0f * (cu[2] - hu4[2]) + fu[2]),
                    hu4[3] + w6 * (Pu[3] + 4.0f * (cu[3] - hu4[3]) + fu[3]));
                st4(out + off + HW,
                    hv4[0] + w6 * (Pv[0] + 4.0f * (cv[0] - hv4[0]) + fv[0]),
                    hv4[1] + w6 * (Pv[1] + 4.0f * (cv[1] - hv4[1]) + fv[1]),
                    hv4[2] + w6 * (Pv[2] + 4.0f * (cv[2] - hv4[2]) + fv[2]),
                    hv4[3] + w6 * (Pv[3] + 4.0f * (cv[3] - hv4[3]) + fv[3]));
            });
    }
}

extern "C" void kernel_launch(void* const* d_in, const int* in_sizes, int n_in,
                              void* d_out, int out_size)
{
    const float* h = nullptr;
    const float* sc[5] = {nullptr, nullptr, nullptr, nullptr, nullptr};
    int nsc = 0;
    for (int i = 0; i < n_in; i++) {
        if (in_sizes[i] == NB * 2 * HW) {
            h = (const float*)d_in[i];
        } else if (nsc < 5) {
            sc[nsc++] = (const float*)d_in[i];
        }
    }
    const float* Re = sc[0];
    const float* UA = sc[1];
    const float* UB = sc[2];
    const float* VA = sc[3];
    const float* VB = sc[4];

    static bool attr_done = false;
    if (!attr_done) {
        cudaFuncSetAttribute(rk4_fused_kernel,
                             cudaFuncAttributeMaxDynamicSharedMemorySize, SMEM_BYTES);
        attr_done = true;
    }

    dim3 grid(1024 / TX, 1024 / TY, NB);   // 16 x 32 x 8 = 4096 blocks
    rk4_fused_kernel<<<grid, 256, SMEM_BYTES>>>(h, (float*)d_out, Re, UA, UB, VA, VB);
    (void)out_size;
}

// round 9
// speedup vs baseline: 1.5521x; 1.0152x over previous
#include <cuda_runtime.h>

// Fully-fused RK4 step of 2D Burgers-type PDE, (8,2,1024,1024) fp32,
// periodic wrap, 4th-order cross stencils (radius 2).
//
// R8: all stencil math in packed f32x2 (FFMA2 etc. via PTX, 2x fp32 rate),
// and x-side loads shrunk to 8B (only e[-2..-1], e[4..5] are needed beyond
// the center float4; +-1 neighbors are register re-pairings).
// Same structure as R7: one kernel, 64x32 tile, s1/s2/s3 in SMEM ping-pong,
// rolling 5-row windows, P = k1+2k2 round-trips through d_out (cache-hot).

#define HW  (1024 * 1024)
#define NB  8
#define TX 64
#define TY 32

#define PA 92
#define PB 84
#define PC 76
#define A_FL (44 * PA)
#define B_FL (40 * PB)
#define SMEM_FLOATS (2 * A_FL + 2 * B_FL)   // 14816
#define SMEM_BYTES  (SMEM_FLOATS * 4)       // 59264

typedef unsigned long long pk2;             // packed float2

__device__ __forceinline__ pk2 add2(pk2 a, pk2 b) {
    pk2 r; asm("add.rn.f32x2 %0, %1, %2;" : "=l"(r) : "l"(a), "l"(b)); return r;
}
__device__ __forceinline__ pk2 mul2(pk2 a, pk2 b) {
    pk2 r; asm("mul.rn.f32x2 %0, %1, %2;" : "=l"(r) : "l"(a), "l"(b)); return r;
}
__device__ __forceinline__ pk2 fma2(pk2 a, pk2 b, pk2 c) {
    pk2 r; asm("fma.rn.f32x2 %0, %1, %2, %3;" : "=l"(r) : "l"(a), "l"(b), "l"(c)); return r;
}
// (hi of a, lo of b) -> one packed pair (register re-pairing, alu pipe)
__device__ __forceinline__ pk2 mix2(pk2 a, pk2 b) {
    pk2 r;
    asm("mov.b64 %0, {%1, %2};" : "=l"(r)
        : "r"((unsigned)(a >> 32)), "r"((unsigned)b));
    return r;
}
__device__ __forceinline__ pk2 bc2(float x) {
    unsigned u = __float_as_uint(x);
    pk2 r; asm("mov.b64 %0, {%1, %1};" : "=l"(r) : "r"(u)); return r;
}
__device__ __forceinline__ void stp(float* dst, pk2 a, pk2 b) {
    ulonglong2 t; t.x = a; t.y = b;
    *reinterpret_cast<ulonglong2*>(dst) = t;
}

struct Pp {
    pk2 A0, A1, A2;          // nu * lap taps / dx^2
    pk2 D1, D2, MD1, MD2;    // +-deriv taps / dx
    pk2 UA, UB, VA, VB;
    pk2 CQ, CHa, F4, M4, F2, W6;  // 0.25, 0.5, 4, -4, 2, DT/12
};

// Global loader, periodic wrap (fx mult of 4 -> 16B aligned; fe even -> 8B).
struct GL {
    const float* p; int x0, y0;
    __device__ __forceinline__ ulonglong2 ld16(int r, int fx) const {
        return *reinterpret_cast<const ulonglong2*>(
            p + (((y0 + r) & 1023) << 10) + ((x0 + fx) & 1023));
    }
    __device__ __forceinline__ pk2 ld8(int r, int fe) const {
        return *reinterpret_cast<const pk2*>(
            p + (((y0 + r) & 1023) << 10) + ((x0 + fe) & 1023));
    }
};
// SMEM loader (tile coords, halo offsets baked in; pitches keep 16B rows).
struct SL {
    const float* s; int pitch, rofs, cofs;
    __device__ __forceinline__ ulonglong2 ld16(int r, int fx) const {
        return *reinterpret_cast<const ulonglong2*>(s + (r + rofs) * pitch + fx + cofs);
    }
    __device__ __forceinline__ pk2 ld8(int r, int fe) const {
        return *reinterpret_cast<const pk2*>(s + (r + rofs) * pitch + fe + cofs);
    }
};

struct Win { pk2 n2a, n2b, n1a, n1b, c0, c1, p1a, p1b; };

// Per-channel derivatives at one float4 point (2 packed halves a=(0,1) b=(2,3)).
// Ls = (e-2,e-1), Rs = (e4,e5). Row direction = "x" (H axis) per reference.
__device__ __forceinline__ void derivs(
    const Win& W, pk2 p2a, pk2 p2b, pk2 Ls, pk2 Rs, const Pp& p,
    pk2& lapa, pk2& lapb, pk2& dxa, pk2& dxb, pk2& dya, pk2& dyb)
{
    const pk2 X1 = mix2(Ls,  W.c0);   // (e-1, e0)
    const pk2 X2 = mix2(W.c0, W.c1);  // (e1, e2)
    const pk2 X3 = mix2(W.c1, Rs);    // (e3, e4)

    const pk2 s1a = add2(add2(W.n1a, W.p1a), add2(X1, X2));
    const pk2 s1b = add2(add2(W.n1b, W.p1b), add2(X2, X3));
    const pk2 s2a = add2(add2(W.n2a, p2a), add2(Ls, W.c1));
    const pk2 s2b = add2(add2(W.n2b, p2b), add2(W.c0, Rs));
    lapa = fma2(p.A2, s2a, fma2(p.A1, s1a, mul2(p.A0, W.c0)));
    lapb = fma2(p.A2, s2b, fma2(p.A1, s1b, mul2(p.A0, W.c1)));

    // d/d(rows): dd2*(n2 - p2) + dd1*(p1 - n1)
    dxa = fma2(p.D2, W.n2a, fma2(p.MD2, p2a, fma2(p.D1, W.p1a, mul2(p.MD1, W.n1a))));
    dxb = fma2(p.D2, W.n2b, fma2(p.MD2, p2b, fma2(p.D1, W.p1b, mul2(p.MD1, W.n1b))));

    // d/d(cols): dd2*(e[j-2]-e[j+2]) + dd1*(e[j+1]-e[j-1])
    dya = fma2(p.D2, Ls,   fma2(p.MD2, W.c1, fma2(p.D1, X2, mul2(p.MD1, X1))));
    dyb = fma2(p.D2, W.c0, fma2(p.MD2, Rs,   fma2(p.D1, X3, mul2(p.MD1, X2))));
}

// Rolling column sweep: CHN rows starting at r0, one float4 column fx.
// emit(r, fua,fub,fva,fvb, cu0,cu1,cv0,cv1)
template <int CHN, class LU, class LV, class F>
__device__ __forceinline__ void sweep_col(
    const LU& lu, const LV& lv, int fx, int r0, const Pp& p, F&& emit)
{
    Win U, V;
    {
        ulonglong2 t;
        t = lu.ld16(r0 - 2, fx); U.n2a = t.x; U.n2b = t.y;
        t = lu.ld16(r0 - 1, fx); U.n1a = t.x; U.n1b = t.y;
        t = lu.ld16(r0,     fx); U.c0  = t.x; U.c1  = t.y;
        t = lu.ld16(r0 + 1, fx); U.p1a = t.x; U.p1b = t.y;
        t = lv.ld16(r0 - 2, fx); V.n2a = t.x; V.n2b = t.y;
        t = lv.ld16(r0 - 1, fx); V.n1a = t.x; V.n1b = t.y;
        t = lv.ld16(r0,     fx); V.c0  = t.x; V.c1  = t.y;
        t = lv.ld16(r0 + 1, fx); V.p1a = t.x; V.p1b = t.y;
    }
#pragma unroll
    for (int i = 0; i < CHN; i++) {
        const int r = r0 + i;
        const ulonglong2 tu = lu.ld16(r + 2, fx);
        const ulonglong2 tv = lv.ld16(r + 2, fx);
        const pk2 uLs = lu.ld8(r, fx - 2), uRs = lu.ld8(r, fx + 4);
        const pk2 vLs = lv.ld8(r, fx - 2), vRs = lv.ld8(r, fx + 4);

        pk2 lua, lub, uxa, uxb, uya, uyb;
        derivs(U, tu.x, tu.y, uLs, uRs, p, lua, lub, uxa, uxb, uya, uyb);
        pk2 lva, lvb, vxa, vxb, vya, vyb;
        derivs(V, tv.x, tv.y, vLs, vRs, p, lva, lvb, vxa, vxb, vya, vyb);

        pk2 fua = fma2(mul2(p.UA, U.c0), uxa, lua); fua = fma2(mul2(p.UB, V.c0), uya, fua);
        pk2 fub = fma2(mul2(p.UA, U.c1), uxb, lub); fub = fma2(mul2(p.UB, V.c1), uyb, fub);
        pk2 fva = fma2(mul2(p.VA, U.c0), vxa, lva); fva = fma2(mul2(p.VB, V.c0), vya, fva);
        pk2 fvb = fma2(mul2(p.VA, U.c1), vxb, lvb); fvb = fma2(mul2(p.VB, V.c1), vyb, fvb);

        emit(r, fua, fub, fva, fvb, U.c0, U.c1, V.c0, V.c1);

        U.n2a = U.n1a; U.n2b = U.n1b; U.n1a = U.c0; U.n1b = U.c1;
        U.c0 = U.p1a;  U.c1 = U.p1b;  U.p1a = tu.x; U.p1b = tu.y;
        V.n2a = V.n1a; V.n2b = V.n1b; V.n1a = V.c0; V.n1b = V.c1;
        V.c0 = V.p1a;  V.c1 = V.p1b;  V.p1a = tv.x; V.p1b = tv.y;
    }
}

__global__ __launch_bounds__(256, 3) void rk4_fused_kernel(
    const float* __restrict__ h,
    float* __restrict__ out,
    const float* __restrict__ pRe,
    const float* __restrict__ pUA,
    const float* __restrict__ pUB,
    const float* __restrict__ pVA,
    const float* __restrict__ pVB)
{
    extern __shared__ float smem[];
    float* uA = smem;
    float* vA = uA + A_FL;
    float* uB = vA + A_FL;
    float* vB = uB + B_FL;

    const int tid  = threadIdx.x;
    const int x0   = blockIdx.x * TX;
    const int y0   = blockIdx.y * TY;
    const int base = blockIdx.z * 2 * HW;

    const float nu = 0.001f / pRe[0];
    const float d1 = 800.0f / 12.0f, d2 = 100.0f / 12.0f;
    Pp p;
    p.A0 = bc2(nu * -50000.0f);
    p.A1 = bc2(nu * (40000.0f / 3.0f));
    p.A2 = bc2(nu * (-10000.0f / 12.0f));
    p.D1 = bc2(d1);  p.D2 = bc2(d2);
    p.MD1 = bc2(-d1); p.MD2 = bc2(-d2);
    p.UA = bc2(pUA[0]); p.UB = bc2(pUB[0]);
    p.VA = bc2(pVA[0]); p.VB = bc2(pVB[0]);
    p.CQ = bc2(0.25f); p.CHa = bc2(0.5f);
    p.F4 = bc2(4.0f);  p.M4 = bc2(-4.0f);
    p.F2 = bc2(2.0f);  p.W6 = bc2(0.5f / 6.0f);

    const GL glu{h + base,      x0, y0};
    const GL glv{h + base + HW, x0, y0};

    // ===== stage 1: k1 from h; s1 = h + 0.25*k1 -> A (22 cols x 44 rows) =====
    if (tid < 242) {                        // 22 cols x 11 chunks of 4
        const int cc = tid % 22;
        const int ch = tid / 22;
        const int fx = 4 * (cc - 3);
        const int r0 = -6 + 4 * ch;
        sweep_col<4>(glu, glv, fx, r0, p,
            [&](int r, pk2 fua, pk2 fub, pk2 fva, pk2 fvb,
                pk2 cu0, pk2 cu1, pk2 cv0, pk2 cv1) {
                const int ix = (r + 6) * PA + fx + 12;
                stp(uA + ix, fma2(p.CQ, fua, cu0), fma2(p.CQ, fub, cu1));
                stp(vA + ix, fma2(p.CQ, fva, cv0), fma2(p.CQ, fvb, cv1));
            });
    }
    __syncthreads();

    // ===== stage 2: k2 from s1(A); s2 -> B; P = k1 + 2*k2 -> out =====
    if (tid < 200) {                        // 20 cols x 10 chunks of 4
        const int cc = tid % 20;
        const int ch = tid / 20;
        const int c  = cc - 2;
        const int fx = 4 * c;
        const int r0 = -4 + 4 * ch;
        const SL alu{uA, PA, 6, 12};
        const SL alv{vA, PA, 6, 12};
        sweep_col<4>(alu, alv, fx, r0, p,
            [&](int r, pk2 fua, pk2 fub, pk2 fva, pk2 fvb,
                pk2 cu0, pk2 cu1, pk2 cv0, pk2 cv1) {
                const ulonglong2 hu = glu.ld16(r, fx);
                const ulonglong2 hv = glv.ld16(r, fx);
                const int ix = (r + 4) * PB + fx + 8;
                stp(uB + ix, fma2(p.CQ, fua, hu.x), fma2(p.CQ, fub, hu.y));
                stp(vB + ix, fma2(p.CQ, fva, hv.x), fma2(p.CQ, fvb, hv.y));
                if ((unsigned)c < 16u && (unsigned)r < 32u) {
                    // k1 = 4*s1c - 4*h ; P = k1 + 2*k2
                    const int off = base + ((y0 + r) << 10) + x0 + fx;
                    pk2 Pa = fma2(p.F2, fua, fma2(p.F4, cu0, mul2(p.M4, hu.x)));
                    pk2 Pb = fma2(p.F2, fub, fma2(p.F4, cu1, mul2(p.M4, hu.y)));
                    stp(out + off, Pa, Pb);
                    Pa = fma2(p.F2, fva, fma2(p.F4, cv0, mul2(p.M4, hv.x)));
                    Pb = fma2(p.F2, fvb, fma2(p.F4, cv1, mul2(p.M4, hv.y)));
                    stp(out + off + HW, Pa, Pb);
                }
            });
    }
    __syncthreads();

    // ===== stage 3: k3 from s2(B); s3 = h + 0.5*k3 -> A storage (C layout) =====
    if (tid < 162) {                        // 18 cols x 9 chunks of 4
        const int cc = tid % 18;
        const int ch = tid / 18;
        const int fx = 4 * (cc - 1);
        const int r0 = -2 + 4 * ch;
        const SL blu{uB, PB, 4, 8};
        const SL blv{vB, PB, 4, 8};
        sweep_col<4>(blu, blv, fx, r0, p,
            [&](int r, pk2 fua, pk2 fub, pk2 fva, pk2 fvb,
                pk2 cu0, pk2 cu1, pk2 cv0, pk2 cv1) {
                const ulonglong2 hu = glu.ld16(r, fx);
                const ulonglong2 hv = glv.ld16(r, fx);
                const int ix = (r + 2) * PC + fx + 4;
                stp(uA + ix, fma2(p.CHa, fua, hu.x), fma2(p.CHa, fub, hu.y));
                stp(vA + ix, fma2(p.CHa, fva, hv.x), fma2(p.CHa, fvb, hv.y));
            });
    }
    __syncthreads();

    // ===== stage 4: k4 from s3(C); out = h + (DT/6)*(P + 4*s3c - 4*h + k4) =====
    {
        const int cc = tid & 15;            // 16 cols x 16 chunks of 2
        const int ch = tid >> 4;
        const int fx = 4 * cc;
        const int r0 = 2 * ch;
        const SL clu{uA, PC, 2, 4};
        const SL clv{vA, PC, 2, 4};
        sweep_col<2>(clu, clv, fx, r0, p,
            [&](int r, pk2 fua, pk2 fub, pk2 fva, pk2 fvb,
                pk2 cu0, pk2 cu1, pk2 cv0, pk2 cv1) {
                const ulonglong2 hu = glu.ld16(r, fx);
                const ulonglong2 hv = glv.ld16(r, fx);
                const int off = base + ((y0 + r) << 10) + x0 + fx;
                const ulonglong2 Pu = *reinterpret_cast<const ulonglong2*>(out + off);
                const ulonglong2 Pv = *reinterpret_cast<const ulonglong2*>(out + off + HW);
                pk2 t, oa, ob;
                t = add2(Pu.x, fua); t = fma2(p.F4, cu0, t); t = fma2(p.M4, hu.x, t);
                oa = fma2(p.W6, t, hu.x);
                t = add2(Pu.y, fub); t = fma2(p.F4, cu1, t); t = fma2(p.M4, hu.y, t);
                ob = fma2(p.W6, t, hu.y);
                stp(out + off, oa, ob);
                t = add2(Pv.x, fva); t = fma2(p.F4, cv0, t); t = fma2(p.M4, hv.x, t);
                oa = fma2(p.W6, t, hv.x);
                t = add2(Pv.y, fvb); t = fma2(p.F4, cv1, t); t = fma2(p.M4, hv.y, t);
                ob = fma2(p.W6, t, hv.y);
                stp(out + off + HW, oa, ob);
            });
    }
}

extern "C" void kernel_launch(void* const* d_in, const int* in_sizes, int n_in,
                              void* d_out, int out_size)
{
    const float* h = nullptr;
    const float* sc[5] = {nullptr, nullptr, nullptr, nullptr, nullptr};
    int nsc = 0;
    for (int i = 0; i < n_in; i++) {
        if (in_sizes[i] == NB * 2 * HW) {
            h = (const float*)d_in[i];
        } else if (nsc < 5) {
            sc[nsc++] = (const float*)d_in[i];
        }
    }
    const float* Re = sc[0];
    const float* UA = sc[1];
    const float* UB = sc[2];
    const float* VA = sc[3];
    const float* VB = sc[4];

    static bool attr_done = false;
    if (!attr_done) {
        cudaFuncSetAttribute(rk4_fused_kernel,
                             cudaFuncAttributeMaxDynamicSharedMemorySize, SMEM_BYTES);
        attr_done = true;
    }

    dim3 grid(1024 / TX, 1024 / TY, NB);    // 16 x 32 x 8 = 4096 blocks
    rk4_fused_kernel<<<grid, 256, SMEM_BYTES>>>(h, (float*)d_out, Re, UA, UB, VA, VB);
    (void)out_size;
}